// round 9
// baseline (speedup 1.0000x reference)
#include <cuda_runtime.h>
#include <cuda_bf16.h>

#define T_DIM 1024
#define B_DIM 64
#define H_DIM 1024
#define OSPLIT 32                 // o-range per k1 block (R3 winner)
#define TPW 8                     // t-rows per warp in k2 (R8 winner)
#define CHUNKS_PER_B (T_DIM / (8 * TPW))   // 16 k2 CTAs per b

// Scratch (allocation-free rule: __device__ globals)
__device__ float g_partial[OSPLIT * B_DIM * H_DIM];  // 8 MB: [s][b][h]
__device__ float g_v[B_DIM * H_DIM];                 // 256 KB
__device__ float g_energies[B_DIM * T_DIM];          // 256 KB: [b][t]
__device__ unsigned g_cnt[B_DIM];                    // per-b arrival counters

// ---------------------------------------------------------------------------
// k1: partial[s][b][h] = sum_{o in s-range} hid[b][o] * W[o][h]
// grid (H/256, 32, 2), 256 threads. W read exactly once. (R3 config)
// ---------------------------------------------------------------------------
__global__ void __launch_bounds__(256) k1_proj_partial(
    const float* __restrict__ hid, const float* __restrict__ W)
{
    const int h  = blockIdx.x * 256 + threadIdx.x;
    const int o0 = blockIdx.y * OSPLIT;
    const int b0 = blockIdx.z * 32;

    __shared__ float sh[32 * OSPLIT];
    for (int i = threadIdx.x; i < 32 * OSPLIT; i += 256) {
        int bb = i >> 5;
        int oo = i & 31;
        sh[i] = hid[(b0 + bb) * H_DIM + o0 + oo];
    }
    __syncthreads();

    float w[OSPLIT];
#pragma unroll
    for (int oo = 0; oo < OSPLIT; oo++)
        w[oo] = W[(o0 + oo) * H_DIM + h];

    float* part = g_partial + blockIdx.y * (B_DIM * H_DIM) + h;

#pragma unroll
    for (int bb = 0; bb < 32; bb++) {
        const float4* s4 = reinterpret_cast<const float4*>(sh + bb * OSPLIT);
        float acc = 0.f;
#pragma unroll
        for (int q = 0; q < OSPLIT / 4; q++) {
            float4 x = s4[q];
            acc += x.x * w[4 * q + 0] + x.y * w[4 * q + 1]
                 + x.z * w[4 * q + 2] + x.w * w[4 * q + 3];
        }
        part[(b0 + bb) * H_DIM] = acc;
    }
}

// ---------------------------------------------------------------------------
// k1b: v[i] = sum_s partial[s][i]; also resets k2's per-b arrival counters
// (stream order guarantees resets land before k2 starts).
// ---------------------------------------------------------------------------
__global__ void __launch_bounds__(256) k1b_reduce()
{
    if (blockIdx.x == 0 && threadIdx.x < B_DIM)
        g_cnt[threadIdx.x] = 0u;

    int i = blockIdx.x * 256 + threadIdx.x;  // 65536 total
    float s = 0.f;
#pragma unroll
    for (int p = 0; p < OSPLIT; p++)
        s += g_partial[p * (B_DIM * H_DIM) + i];
    g_v[i] = s;
}

// ---------------------------------------------------------------------------
// k2: energies[b][t] = <enc[t,b,:], v[b,:]>  +  fused softmax epilogue.
// Inner loop identical to R8 winner (v in 8 float4 regs, unroll 4, __ldcs).
// After its stores, each CTA arrives on g_cnt[b]; the 16th (last) CTA for b
// runs the row softmax (256 thr x 1 float4, L2-hot) and writes d_out.
// Bias dropped (softmax shift invariance).
// ---------------------------------------------------------------------------
__global__ void __launch_bounds__(256) k2_energies(
    const float* __restrict__ enc, float* __restrict__ out)
{
    const int warp = threadIdx.x >> 5;
    const int lane = threadIdx.x & 31;
    const int b    = blockIdx.x;                       // 0..63
    const int t0   = blockIdx.y * (8 * TPW) + warp * TPW;

    // v[b] -> registers (8 L2-hot loads per warp, amortized over TPW rows)
    const float4* v4 = reinterpret_cast<const float4*>(g_v + b * H_DIM);
    float4 v[8];
#pragma unroll
    for (int k = 0; k < 8; k++)
        v[k] = v4[lane + 32 * k];

    const float4* e4 = reinterpret_cast<const float4*>(
        enc + (size_t)(t0 * B_DIM + b) * H_DIM) + lane;
    const size_t row_stride4 = (size_t)B_DIM * H_DIM / 4;   // float4 units

    float* eout = g_energies + b * T_DIM + t0;

#pragma unroll 4
    for (int i = 0; i < TPW; i++) {
        float acc = 0.f;
#pragma unroll
        for (int k = 0; k < 8; k++) {
            float4 x = __ldcs(e4 + 32 * k);
            acc += x.x * v[k].x + x.y * v[k].y + x.z * v[k].z + x.w * v[k].w;
        }
#pragma unroll
        for (int off = 16; off; off >>= 1)
            acc += __shfl_xor_sync(0xffffffffu, acc, off);
        if (lane == 0)
            eout[i] = acc;
        e4 += row_stride4;
    }

    // ---- arrival: last CTA for this b runs the softmax ----
    __syncthreads();
    __threadfence();                       // publish our energy stores
    __shared__ unsigned s_old;
    if (threadIdx.x == 0)
        s_old = atomicAdd(&g_cnt[b], 1u);
    __syncthreads();
    if (s_old != CHUNKS_PER_B - 1)
        return;

    __threadfence();                       // acquire: see all CTAs' stores

    const int tid = threadIdx.x;
    __shared__ float sred[8];

    float4 x = reinterpret_cast<const float4*>(g_energies + b * T_DIM)[tid];

    float m = fmaxf(fmaxf(x.x, x.y), fmaxf(x.z, x.w));
#pragma unroll
    for (int off = 16; off; off >>= 1)
        m = fmaxf(m, __shfl_xor_sync(0xffffffffu, m, off));
    if (lane == 0) sred[warp] = m;
    __syncthreads();
    m = sred[0];
#pragma unroll
    for (int w2 = 1; w2 < 8; w2++)
        m = fmaxf(m, sred[w2]);
    __syncthreads();

    x.x = __expf(x.x - m);
    x.y = __expf(x.y - m);
    x.z = __expf(x.z - m);
    x.w = __expf(x.w - m);
    float lsum = x.x + x.y + x.z + x.w;
#pragma unroll
    for (int off = 16; off; off >>= 1)
        lsum += __shfl_xor_sync(0xffffffffu, lsum, off);
    if (lane == 0) sred[warp] = lsum;
    __syncthreads();
    float tot = 0.f;
#pragma unroll
    for (int w2 = 0; w2 < 8; w2++)
        tot += sred[w2];
    const float inv = 1.f / tot;

    x.x *= inv; x.y *= inv; x.z *= inv; x.w *= inv;
    reinterpret_cast<float4*>(out + b * T_DIM)[tid] = x;
}

// ---------------------------------------------------------------------------
extern "C" void kernel_launch(void* const* d_in, const int* in_sizes, int n_in,
                              void* d_out, int out_size)
{
    const float* hid = (const float*)d_in[0];   // [1, B, H]
    const float* enc = (const float*)d_in[1];   // [T, B, H]
    const float* W   = (const float*)d_in[2];   // [H, H]
    // d_in[3] = bias: dropped — softmax shift-invariance makes it a no-op.
    float* out = (float*)d_out;                 // [B, 1, T]

    k1_proj_partial<<<dim3(H_DIM / 256, OSPLIT, 2), 256>>>(hid, W);
    k1b_reduce<<<(B_DIM * H_DIM) / 256, 256>>>();
    k2_energies<<<dim3(B_DIM, T_DIM / (8 * TPW)), 256>>>(enc, out);
}

// round 10
// speedup vs baseline: 1.0097x; 1.0097x over previous
#include <cuda_runtime.h>
#include <cuda_bf16.h>

#define T_DIM 1024
#define B_DIM 64
#define H_DIM 1024
#define OSPLIT 32                 // o-range per k1 block
#define K1_HT 128                 // h-tile per k1 block (was 256)
#define TPW 8                     // t-rows per warp in k2 (R8 winner)

// Scratch (allocation-free rule: __device__ globals)
__device__ float g_partial[OSPLIT * B_DIM * H_DIM];  // 8 MB: [s][b][h]
__device__ float g_v[B_DIM * H_DIM];                 // 256 KB
__device__ float g_energies[B_DIM * T_DIM];          // 256 KB: [b][t]

// ---------------------------------------------------------------------------
// k1: partial[s][b][h] = sum_{o in s-range} hid[b][o] * W[o][h]
// grid (H/128, 32, 2) = 512 CTAs x 128 threads: twice the CTAs of R8's k1,
// so waves ~3.4 and ~6 CTAs/SM fit by registers -> latency actually hidden.
// Per-thread code unchanged (w[32] regs, smem hid broadcast, W read once).
// ---------------------------------------------------------------------------
__global__ void __launch_bounds__(K1_HT) k1_proj_partial(
    const float* __restrict__ hid, const float* __restrict__ W)
{
    const int h  = blockIdx.x * K1_HT + threadIdx.x;
    const int o0 = blockIdx.y * OSPLIT;
    const int b0 = blockIdx.z * 32;

    __shared__ float sh[32 * OSPLIT];   // 4 KB
    for (int i = threadIdx.x; i < 32 * OSPLIT; i += K1_HT) {
        int bb = i >> 5;
        int oo = i & 31;
        sh[i] = hid[(b0 + bb) * H_DIM + o0 + oo];
    }
    __syncthreads();

    float w[OSPLIT];
#pragma unroll
    for (int oo = 0; oo < OSPLIT; oo++)
        w[oo] = W[(o0 + oo) * H_DIM + h];

    float* part = g_partial + blockIdx.y * (B_DIM * H_DIM) + h;

#pragma unroll
    for (int bb = 0; bb < 32; bb++) {
        const float4* s4 = reinterpret_cast<const float4*>(sh + bb * OSPLIT);
        float acc = 0.f;
#pragma unroll
        for (int q = 0; q < OSPLIT / 4; q++) {
            float4 x = s4[q];
            acc += x.x * w[4 * q + 0] + x.y * w[4 * q + 1]
                 + x.z * w[4 * q + 2] + x.w * w[4 * q + 3];
        }
        part[(b0 + bb) * H_DIM] = acc;
    }
}

// ---------------------------------------------------------------------------
// k1b: v[i] = sum_s partial[s][i]   (deterministic reduction, no atomics)
// ---------------------------------------------------------------------------
__global__ void __launch_bounds__(256) k1b_reduce()
{
    int i = blockIdx.x * 256 + threadIdx.x;  // 65536 total
    float s = 0.f;
#pragma unroll
    for (int p = 0; p < OSPLIT; p++)
        s += g_partial[p * (B_DIM * H_DIM) + i];
    g_v[i] = s;
}

// ---------------------------------------------------------------------------
// k2: energies[b][t] = <enc[t,b,:], v[b,:]>   (R8 winner, byte-identical)
// grid (64 b, 16 t-chunks) = 1024 CTAs; v in 8 float4 regs; unroll 4 ->
// 32 batched LDG.128 in flight; __ldcs evict-first on the enc stream.
// ---------------------------------------------------------------------------
__global__ void __launch_bounds__(256) k2_energies(const float* __restrict__ enc)
{
    const int warp = threadIdx.x >> 5;
    const int lane = threadIdx.x & 31;
    const int b    = blockIdx.x;                       // 0..63
    const int t0   = blockIdx.y * (8 * TPW) + warp * TPW;

    const float4* v4 = reinterpret_cast<const float4*>(g_v + b * H_DIM);
    float4 v[8];
#pragma unroll
    for (int k = 0; k < 8; k++)
        v[k] = v4[lane + 32 * k];

    const float4* e4 = reinterpret_cast<const float4*>(
        enc + (size_t)(t0 * B_DIM + b) * H_DIM) + lane;
    const size_t row_stride4 = (size_t)B_DIM * H_DIM / 4;   // float4 units

    float* eout = g_energies + b * T_DIM + t0;

#pragma unroll 4
    for (int i = 0; i < TPW; i++) {
        float acc = 0.f;
#pragma unroll
        for (int k = 0; k < 8; k++) {
            float4 x = __ldcs(e4 + 32 * k);
            acc += x.x * v[k].x + x.y * v[k].y + x.z * v[k].z + x.w * v[k].w;
        }
#pragma unroll
        for (int off = 16; off; off >>= 1)
            acc += __shfl_xor_sync(0xffffffffu, acc, off);
        if (lane == 0)
            eout[i] = acc;
        e4 += row_stride4;
    }
}

// ---------------------------------------------------------------------------
// k3: softmax over T per row b — warp per row, one block per row (grid 64).
// Bias dropped (softmax shift invariance). (R8 winner, byte-identical.)
// ---------------------------------------------------------------------------
__global__ void __launch_bounds__(32) k3_softmax(float* __restrict__ out)
{
    const int lane = threadIdx.x;
    const int b    = blockIdx.x;

    const float4* e4 = reinterpret_cast<const float4*>(g_energies + b * T_DIM);
    float4 vals[8];
#pragma unroll
    for (int k = 0; k < 8; k++)
        vals[k] = e4[lane + 32 * k];

    float m = -1e30f;
#pragma unroll
    for (int k = 0; k < 8; k++)
        m = fmaxf(m, fmaxf(fmaxf(vals[k].x, vals[k].y), fmaxf(vals[k].z, vals[k].w)));
#pragma unroll
    for (int off = 16; off; off >>= 1)
        m = fmaxf(m, __shfl_xor_sync(0xffffffffu, m, off));

    float lsum = 0.f;
#pragma unroll
    for (int k = 0; k < 8; k++) {
        vals[k].x = __expf(vals[k].x - m);
        vals[k].y = __expf(vals[k].y - m);
        vals[k].z = __expf(vals[k].z - m);
        vals[k].w = __expf(vals[k].w - m);
        lsum += vals[k].x + vals[k].y + vals[k].z + vals[k].w;
    }
#pragma unroll
    for (int off = 16; off; off >>= 1)
        lsum += __shfl_xor_sync(0xffffffffu, lsum, off);
    const float inv = 1.f / lsum;

    float4* o4 = reinterpret_cast<float4*>(out + b * T_DIM);
#pragma unroll
    for (int k = 0; k < 8; k++) {
        float4 r = vals[k];
        r.x *= inv; r.y *= inv; r.z *= inv; r.w *= inv;
        o4[lane + 32 * k] = r;
    }
}

// ---------------------------------------------------------------------------
extern "C" void kernel_launch(void* const* d_in, const int* in_sizes, int n_in,
                              void* d_out, int out_size)
{
    const float* hid = (const float*)d_in[0];   // [1, B, H]
    const float* enc = (const float*)d_in[1];   // [T, B, H]
    const float* W   = (const float*)d_in[2];   // [H, H]
    // d_in[3] = bias: dropped — softmax shift-invariance makes it a no-op.
    float* out = (float*)d_out;                 // [B, 1, T]

    k1_proj_partial<<<dim3(H_DIM / K1_HT, OSPLIT, 2), K1_HT>>>(hid, W);
    k1b_reduce<<<(B_DIM * H_DIM) / 256, 256>>>();
    k2_energies<<<dim3(B_DIM, T_DIM / (8 * TPW)), 256>>>(enc);
    k3_softmax<<<B_DIM, 32>>>(out);
}

// round 11
// speedup vs baseline: 1.0166x; 1.0069x over previous
#include <cuda_runtime.h>
#include <cuda_bf16.h>

#define T_DIM 1024
#define B_DIM 64
#define H_DIM 1024
#define OSPLIT 32                 // o-range per k1 block
#define K1_HT 128                 // h-tile per k1 block
#define TPW 8                     // t-rows per warp in k2 (R8 winner)

// Scratch (allocation-free rule: __device__ globals)
__device__ float g_partial[OSPLIT * B_DIM * H_DIM];  // 8 MB: [s][b][h]
__device__ float g_v[B_DIM * H_DIM];                 // 256 KB
__device__ float g_energies[B_DIM * T_DIM];          // 256 KB: [b][t]

// ---------------------------------------------------------------------------
// k1: partial[s][b][h] = sum_{o in s-range} hid[b][o] * W[o][h]
// grid (H/128, 32, 2) = 512 CTAs x 128 threads.
// KEY CHANGE vs R10: 4 independent accumulators per bb — the old single-acc
// version had a 32-deep serial FFMA chain (128 cyc/bb of RAW stall) that
// ~6 warps/SMSP could not hide. Chain depth now 8.
// ---------------------------------------------------------------------------
__global__ void __launch_bounds__(K1_HT) k1_proj_partial(
    const float* __restrict__ hid, const float* __restrict__ W)
{
    const int h  = blockIdx.x * K1_HT + threadIdx.x;
    const int o0 = blockIdx.y * OSPLIT;
    const int b0 = blockIdx.z * 32;

    __shared__ float sh[32 * OSPLIT];   // 4 KB
    for (int i = threadIdx.x; i < 32 * OSPLIT; i += K1_HT) {
        int bb = i >> 5;
        int oo = i & 31;
        sh[i] = hid[(b0 + bb) * H_DIM + o0 + oo];
    }
    __syncthreads();

    float w[OSPLIT];
#pragma unroll
    for (int oo = 0; oo < OSPLIT; oo++)
        w[oo] = W[(o0 + oo) * H_DIM + h];

    float* part = g_partial + blockIdx.y * (B_DIM * H_DIM) + h;

#pragma unroll
    for (int bb = 0; bb < 32; bb++) {
        const float4* s4 = reinterpret_cast<const float4*>(sh + bb * OSPLIT);
        // 8 independent LDS.128 + 4 independent FFMA chains of depth 8
        float4 x0 = s4[0], x1 = s4[1], x2 = s4[2], x3 = s4[3];
        float4 x4 = s4[4], x5 = s4[5], x6 = s4[6], x7 = s4[7];
        float a0 = 0.f, a1 = 0.f, a2 = 0.f, a3 = 0.f;
        a0 += x0.x * w[0]  + x0.y * w[1]  + x0.z * w[2]  + x0.w * w[3];
        a1 += x1.x * w[4]  + x1.y * w[5]  + x1.z * w[6]  + x1.w * w[7];
        a2 += x2.x * w[8]  + x2.y * w[9]  + x2.z * w[10] + x2.w * w[11];
        a3 += x3.x * w[12] + x3.y * w[13] + x3.z * w[14] + x3.w * w[15];
        a0 += x4.x * w[16] + x4.y * w[17] + x4.z * w[18] + x4.w * w[19];
        a1 += x5.x * w[20] + x5.y * w[21] + x5.z * w[22] + x5.w * w[23];
        a2 += x6.x * w[24] + x6.y * w[25] + x6.z * w[26] + x6.w * w[27];
        a3 += x7.x * w[28] + x7.y * w[29] + x7.z * w[30] + x7.w * w[31];
        part[(b0 + bb) * H_DIM] = (a0 + a1) + (a2 + a3);
    }
}

// ---------------------------------------------------------------------------
// k1b: v[i] = sum_s partial[s][i]   (deterministic reduction, no atomics)
// ---------------------------------------------------------------------------
__global__ void __launch_bounds__(256) k1b_reduce()
{
    int i = blockIdx.x * 256 + threadIdx.x;  // 65536 total
    float s0 = 0.f, s1 = 0.f, s2 = 0.f, s3 = 0.f;
#pragma unroll
    for (int p = 0; p < OSPLIT; p += 4) {
        s0 += g_partial[(p + 0) * (B_DIM * H_DIM) + i];
        s1 += g_partial[(p + 1) * (B_DIM * H_DIM) + i];
        s2 += g_partial[(p + 2) * (B_DIM * H_DIM) + i];
        s3 += g_partial[(p + 3) * (B_DIM * H_DIM) + i];
    }
    g_v[i] = (s0 + s1) + (s2 + s3);
}

// ---------------------------------------------------------------------------
// k2: energies[b][t] = <enc[t,b,:], v[b,:]>   (R8 winner, byte-identical)
// grid (64 b, 16 t-chunks) = 1024 CTAs; v in 8 float4 regs; unroll 4 ->
// 32 batched LDG.128 in flight; __ldcs evict-first on the enc stream.
// ---------------------------------------------------------------------------
__global__ void __launch_bounds__(256) k2_energies(const float* __restrict__ enc)
{
    const int warp = threadIdx.x >> 5;
    const int lane = threadIdx.x & 31;
    const int b    = blockIdx.x;                       // 0..63
    const int t0   = blockIdx.y * (8 * TPW) + warp * TPW;

    const float4* v4 = reinterpret_cast<const float4*>(g_v + b * H_DIM);
    float4 v[8];
#pragma unroll
    for (int k = 0; k < 8; k++)
        v[k] = v4[lane + 32 * k];

    const float4* e4 = reinterpret_cast<const float4*>(
        enc + (size_t)(t0 * B_DIM + b) * H_DIM) + lane;
    const size_t row_stride4 = (size_t)B_DIM * H_DIM / 4;   // float4 units

    float* eout = g_energies + b * T_DIM + t0;

#pragma unroll 4
    for (int i = 0; i < TPW; i++) {
        float acc = 0.f;
#pragma unroll
        for (int k = 0; k < 8; k++) {
            float4 x = __ldcs(e4 + 32 * k);
            acc += x.x * v[k].x + x.y * v[k].y + x.z * v[k].z + x.w * v[k].w;
        }
#pragma unroll
        for (int off = 16; off; off >>= 1)
            acc += __shfl_xor_sync(0xffffffffu, acc, off);
        if (lane == 0)
            eout[i] = acc;
        e4 += row_stride4;
    }
}

// ---------------------------------------------------------------------------
// k3: softmax over T per row b — warp per row, one block per row (grid 64).
// Bias dropped (softmax shift invariance). (R8 winner, byte-identical.)
// ---------------------------------------------------------------------------
__global__ void __launch_bounds__(32) k3_softmax(float* __restrict__ out)
{
    const int lane = threadIdx.x;
    const int b    = blockIdx.x;

    const float4* e4 = reinterpret_cast<const float4*>(g_energies + b * T_DIM);
    float4 vals[8];
#pragma unroll
    for (int k = 0; k < 8; k++)
        vals[k] = e4[lane + 32 * k];

    float m = -1e30f;
#pragma unroll
    for (int k = 0; k < 8; k++)
        m = fmaxf(m, fmaxf(fmaxf(vals[k].x, vals[k].y), fmaxf(vals[k].z, vals[k].w)));
#pragma unroll
    for (int off = 16; off; off >>= 1)
        m = fmaxf(m, __shfl_xor_sync(0xffffffffu, m, off));

    float lsum = 0.f;
#pragma unroll
    for (int k = 0; k < 8; k++) {
        vals[k].x = __expf(vals[k].x - m);
        vals[k].y = __expf(vals[k].y - m);
        vals[k].z = __expf(vals[k].z - m);
        vals[k].w = __expf(vals[k].w - m);
        lsum += vals[k].x + vals[k].y + vals[k].z + vals[k].w;
    }
#pragma unroll
    for (int off = 16; off; off >>= 1)
        lsum += __shfl_xor_sync(0xffffffffu, lsum, off);
    const float inv = 1.f / lsum;

    float4* o4 = reinterpret_cast<float4*>(out + b * T_DIM);
#pragma unroll
    for (int k = 0; k < 8; k++) {
        float4 r = vals[k];
        r.x *= inv; r.y *= inv; r.z *= inv; r.w *= inv;
        o4[lane + 32 * k] = r;
    }
}

// ---------------------------------------------------------------------------
extern "C" void kernel_launch(void* const* d_in, const int* in_sizes, int n_in,
                              void* d_out, int out_size)
{
    const float* hid = (const float*)d_in[0];   // [1, B, H]
    const float* enc = (const float*)d_in[1];   // [T, B, H]
    const float* W   = (const float*)d_in[2];   // [H, H]
    // d_in[3] = bias: dropped — softmax shift-invariance makes it a no-op.
    float* out = (float*)d_out;                 // [B, 1, T]

    k1_proj_partial<<<dim3(H_DIM / K1_HT, OSPLIT, 2), K1_HT>>>(hid, W);
    k1b_reduce<<<(B_DIM * H_DIM) / 256, 256>>>();
    k2_energies<<<dim3(B_DIM, T_DIM / (8 * TPW)), 256>>>(enc);
    k3_softmax<<<B_DIM, 32>>>(out);
}